// round 7
// baseline (speedup 1.0000x reference)
#include <cuda_runtime.h>
#include <cuda_bf16.h>

#define BB     128
#define NTOK   1369
#define DINOD  384
#define CLIPD  512
#define NH     8
#define ROWS   24
#define SPLIT0 685                       // tokens in half 0 (half1 = 684)
#define CHUNKS 29                        // ceil(685/24)
#define CHUNK_FLOATS (ROWS*DINOD)        // 9216
// k3 dynamic smem: 2 buffers + lg(192) + w_s(192) + r_s(8) + m_s(8)
#define SMEM3 ((2*CHUNK_FLOATS + 2*ROWS*NH + 16)*4)   // 75328 B

__device__ __align__(16) float g_Q[BB*CLIPD];
__device__ __align__(16) float g_qk[BB*NH*DINOD];
__device__ __align__(16) float g_ctx2[BB*2*NH*DINOD];   // per (b,half) unnormalized ctx
__device__ __align__(16) float g_ml[BB*2*16];           // per (b,half): m[0..7], l[8..15]

// ---- packed f32x2 helpers ----
__device__ __forceinline__ unsigned long long pk2(float x, float y){
  unsigned long long r; asm("mov.b64 %0, {%1,%2};" : "=l"(r) : "f"(x), "f"(y)); return r;
}
__device__ __forceinline__ float2 upk2(unsigned long long v){
  float2 r; asm("mov.b64 {%0,%1}, %2;" : "=f"(r.x), "=f"(r.y) : "l"(v)); return r;
}
__device__ __forceinline__ void fma2(unsigned long long& d, unsigned long long a, unsigned long long b){
  asm("fma.rn.f32x2 %0, %1, %2, %0;" : "+l"(d) : "l"(a), "l"(b));
}
__device__ __forceinline__ void mul2(unsigned long long& d, unsigned long long a){
  asm("mul.rn.f32x2 %0, %0, %1;" : "+l"(d) : "l"(a));
}
__device__ __forceinline__ void cp16z(float* dst, const float* src, int sz){
  unsigned sa = (unsigned)__cvta_generic_to_shared(dst);
  asm volatile("cp.async.cg.shared.global [%0], [%1], 16, %2;" :: "r"(sa), "l"(src), "r"(sz) : "memory");
}

// ============ K1: Q = clip @ Wq + bq  (grid 128 = 64 b-pairs x 2 col-halves) ============
__global__ void __launch_bounds__(128) k1_qproj(const float* __restrict__ clip,
                                                const float* __restrict__ Wq,
                                                const float* __restrict__ bq){
  __shared__ float cs[2][CLIPD];
  int t = threadIdx.x;
  int p = blockIdx.x >> 1, half = blockIdx.x & 1;
  int b0 = 2*p, b1 = 2*p + 1;
  for(int i = t; i < CLIPD; i += 128){
    cs[0][i] = clip[(size_t)b0*CLIPD + i];
    cs[1][i] = clip[(size_t)b1*CLIPD + i];
  }
  __syncthreads();
  int col = half*256 + 2*t;                 // 2 adjacent cols per thread
  float2 bq2 = *(const float2*)(bq + col);
  unsigned long long A0 = pk2(bq2.x, bq2.y), A1 = A0;
  #pragma unroll 8
  for(int c = 0; c < CLIPD; c++){
    float2 w = *(const float2*)(Wq + (size_t)c*CLIPD + col);
    unsigned long long wp = pk2(w.x, w.y);
    float c0 = cs[0][c], c1 = cs[1][c];
    fma2(A0, wp, pk2(c0, c0));
    fma2(A1, wp, pk2(c1, c1));
  }
  float2 r0 = upk2(A0), r1 = upk2(A1);
  *(float2*)(g_Q + (size_t)b0*CLIPD + col) = r0;
  *(float2*)(g_Q + (size_t)b1*CLIPD + col) = r1;
}

// ============ K2: qk[b,h,c] = sum_d Wk[c,h*64+d]*Q[b,h*64+d] / (8*temp) ============
// grid 64, 2 batches per CTA, 384 thr; warp iterates c with coalesced Wk rows.
__global__ void __launch_bounds__(384) k2_qk(const float* __restrict__ Wk,
                                             const float* __restrict__ temp){
  __shared__ float Qs[2][CLIPD];
  int t = threadIdx.x;
  int b0 = blockIdx.x * 2;
  for(int i = t; i < 2*CLIPD; i += 384) Qs[i>>9][i&511] = g_Q[(size_t)b0*CLIPD + i];
  __syncthreads();
  float inv_scale = 1.0f/(8.0f*temp[0]);
  int w = t>>5, l = t&31;
  for(int c = w; c < DINOD; c += 12){
    const float* wr = Wk + (size_t)c*CLIPD;
    #pragma unroll
    for(int h = 0; h < NH; h++){
      float w0 = wr[h*64 + l], w1 = wr[h*64 + 32 + l];
      #pragma unroll
      for(int bb = 0; bb < 2; bb++){
        float s = w0*Qs[bb][h*64+l] + w1*Qs[bb][h*64+32+l];
        #pragma unroll
        for(int o = 16; o; o >>= 1) s += __shfl_xor_sync(0xffffffffu, s, o);
        if(l == 0) g_qk[((size_t)(b0+bb)*NH + h)*DINOD + c] = s*inv_scale;
      }
    }
  }
}

// ============ K3: streaming single-query attention ============
// grid 256 = 128 batches x 2 token-halves; 256 threads; 2 CTAs/SM.
// Warp w: heads base (w&1)*4, rows (w>>2 is wrong—see rg) ; rg=w>>1 rows rg*6..+5.
// Within warp: lanes 0-15 heads {h0,h0+1}, lanes 16-31 heads {h0+2,h0+3};
// lane c-slice: c = (lane&15)*4 + j*64, j=0..5.
__global__ void __launch_bounds__(256, 2) k3_attn(const float* __restrict__ dino){
  extern __shared__ float sm[];
  float* dbuf = sm;                          // 2 * 9216
  float* lg   = sm + 2*CHUNK_FLOATS;         // 192
  float* w_s  = lg + ROWS*NH;                // 192
  float* r_s  = w_s + ROWS*NH;               // 8
  float* m_s  = r_s + 8;                     // 8

  int t = threadIdx.x, wid = t>>5, lane = t&31;
  int cta = blockIdx.x, b = cta>>1, half = cta&1;
  int cnt = half ? (NTOK - SPLIT0) : SPLIT0;
  const float* dino_b = dino + ((size_t)b*NTOK + (half ? SPLIT0 : 0))*DINOD;
  const long limitf = (long)cnt*DINOD;

  int hl = lane & 15;
  int h0 = (wid & 1)*4 + (lane >> 4)*2;      // this lane's head pair
  int rg = wid >> 1;                         // row group: rows rg*6 .. rg*6+5

  // qk registers: 2 heads x 24 c-floats as f32x2 pairs
  unsigned long long q0[6][2], q1[6][2];
  {
    const float* qkb = g_qk + (size_t)b*NH*DINOD;
    #pragma unroll
    for(int j = 0; j < 6; j++){
      float4 v = *(const float4*)(qkb + h0*DINOD + j*64 + hl*4);
      q0[j][0] = pk2(v.x,v.y); q0[j][1] = pk2(v.z,v.w);
      float4 u = *(const float4*)(qkb + (h0+1)*DINOD + j*64 + hl*4);
      q1[j][0] = pk2(u.x,u.y); q1[j][1] = pk2(u.z,u.w);
    }
  }

  // ctx accumulators: col t (a*) and col t+256 (b*, threads<128), head pairs
  unsigned long long a0=0,a1=0,a2=0,a3=0, c0=0,c1=0,c2=0,c3=0;
  float m_run = -1e30f, l_run = 0.0f;        // meaningful in lane 0 (head = wid)

  // prologue: prefetch chunk 0
  #pragma unroll
  for(int k = 0; k < 9; k++){
    int gi = t + k*256;
    long f = (long)gi*4;
    cp16z(dbuf + gi*4, dino_b + f, (f+4 <= limitf) ? 16 : 0);
  }
  asm volatile("cp.async.commit_group;" ::: "memory");

  for(int i = 0; i < CHUNKS; i++){
    __syncthreads();                         // prev phase B done -> buffer free
    if(i+1 < CHUNKS){
      float* dst = dbuf + ((i+1)&1)*CHUNK_FLOATS;
      long basef = (long)(i+1)*CHUNK_FLOATS;
      #pragma unroll
      for(int k = 0; k < 9; k++){
        int gi = t + k*256;
        long f = basef + (long)gi*4;
        cp16z(dst + gi*4, dino_b + f, (f+4 <= limitf) ? 16 : 0);
      }
    }
    asm volatile("cp.async.commit_group;" ::: "memory");
    asm volatile("cp.async.wait_group 1;" ::: "memory");   // chunk i landed
    __syncthreads();

    const float* dcur = dbuf + (i&1)*CHUNK_FLOATS;
    int base = i*ROWS;

    // ---- Phase A: logits ----
    #pragma unroll
    for(int rr = 0; rr < 6; rr++){
      int row = rg*6 + rr;
      if(base + row < cnt){
        const float4* rf = (const float4*)(dcur + row*DINOD);
        unsigned long long s0p = 0ull, s1p = 0ull;
        #pragma unroll
        for(int j = 0; j < 6; j++){
          float4 d = rf[j*16 + hl];
          unsigned long long dA = pk2(d.x,d.y), dB = pk2(d.z,d.w);
          fma2(s0p, dA, q0[j][0]); fma2(s0p, dB, q0[j][1]);
          fma2(s1p, dA, q1[j][0]); fma2(s1p, dB, q1[j][1]);
        }
        float2 P0 = upk2(s0p), P1 = upk2(s1p);
        float s0 = P0.x + P0.y, s1 = P1.x + P1.y;
        #pragma unroll
        for(int o = 8; o; o >>= 1){
          s0 += __shfl_xor_sync(0xffffffffu, s0, o);
          s1 += __shfl_xor_sync(0xffffffffu, s1, o);
        }
        if(hl == 0) *(float2*)(lg + row*NH + h0) = make_float2(s0, s1);
      } else if(hl == 0){
        *(float2*)(lg + row*NH + h0) = make_float2(-1e30f, -1e30f);
      }
    }
    __syncthreads();
    // ---- per-head max (warp wid owns head wid) ----
    {
      float v = (lane < ROWS) ? lg[lane*NH + wid] : -1e30f;
      #pragma unroll
      for(int o = 16; o; o >>= 1) v = fmaxf(v, __shfl_xor_sync(0xffffffffu, v, o));
      if(lane == 0){
        float mn = fmaxf(m_run, v);
        r_s[wid] = __expf(m_run - mn);
        m_s[wid] = mn;
        m_run = mn;
      }
    }
    __syncthreads();
    if(t < ROWS*NH) w_s[t] = __expf(lg[t] - m_s[t & 7]);
    __syncthreads();
    // ---- l update (parallel, warp wid = head wid) ----
    {
      float v = (lane < ROWS) ? w_s[lane*NH + wid] : 0.0f;
      #pragma unroll
      for(int o = 16; o; o >>= 1) v += __shfl_xor_sync(0xffffffffu, v, o);
      if(lane == 0) l_run = l_run * r_s[wid] + v;
    }
    // ---- Phase B: ctx update ----
    {
      ulonglong2 ra = *(const ulonglong2*)r_s;
      ulonglong2 rb = *(const ulonglong2*)(r_s + 4);
      mul2(a0, ra.x); mul2(a1, ra.y); mul2(a2, rb.x); mul2(a3, rb.y);
      if(t < 128){ mul2(c0, ra.x); mul2(c1, ra.y); mul2(c2, rb.x); mul2(c3, rb.y); }
      #pragma unroll 4
      for(int n = 0; n < ROWS; n++){
        ulonglong2 wa = *(const ulonglong2*)(w_s + n*NH);
        ulonglong2 wb = *(const ulonglong2*)(w_s + n*NH + 4);
        float dv = dcur[n*DINOD + t];
        unsigned long long dd = pk2(dv, dv);
        fma2(a0, wa.x, dd); fma2(a1, wa.y, dd);
        fma2(a2, wb.x, dd); fma2(a3, wb.y, dd);
        if(t < 128){
          float dv2 = dcur[n*DINOD + t + 256];
          unsigned long long dd2 = pk2(dv2, dv2);
          fma2(c0, wa.x, dd2); fma2(c1, wa.y, dd2);
          fma2(c2, wb.x, dd2); fma2(c3, wb.y, dd2);
        }
      }
    }
  }

  // store unnormalized ctx + (m, l)
  float* cb = g_ctx2 + (size_t)cta*NH*DINOD;
  float2 p;
  p = upk2(a0); cb[0*DINOD + t] = p.x; cb[1*DINOD + t] = p.y;
  p = upk2(a1); cb[2*DINOD + t] = p.x; cb[3*DINOD + t] = p.y;
  p = upk2(a2); cb[4*DINOD + t] = p.x; cb[5*DINOD + t] = p.y;
  p = upk2(a3); cb[6*DINOD + t] = p.x; cb[7*DINOD + t] = p.y;
  if(t < 128){
    p = upk2(c0); cb[0*DINOD + t+256] = p.x; cb[1*DINOD + t+256] = p.y;
    p = upk2(c1); cb[2*DINOD + t+256] = p.x; cb[3*DINOD + t+256] = p.y;
    p = upk2(c2); cb[4*DINOD + t+256] = p.x; cb[5*DINOD + t+256] = p.y;
    p = upk2(c3); cb[6*DINOD + t+256] = p.x; cb[7*DINOD + t+256] = p.y;
  }
  if(lane == 0){
    g_ml[cta*16 + wid]     = m_run;
    g_ml[cta*16 + 8 + wid] = l_run;
  }
}

// ============ K4: merge halves, out = ctx @ Wv + bv, LayerNorm ============
// grid 128 (one batch per CTA), 128 threads, 4 cols per thread via float4.
__global__ void __launch_bounds__(128) k4_out(const float* __restrict__ Wv,
                                              const float* __restrict__ bv,
                                              const float* __restrict__ gamma,
                                              const float* __restrict__ beta,
                                              float* __restrict__ out){
  __shared__ float cs[NH*DINOD];             // merged normalized ctx
  __shared__ float sA[NH], sB[NH];
  __shared__ float red[2][4];
  int t = threadIdx.x;
  int b = blockIdx.x;
  if(t < NH){
    float mA = g_ml[(b*2)*16 + t],   lA = g_ml[(b*2)*16 + 8 + t];
    float mB = g_ml[(b*2+1)*16 + t], lB = g_ml[(b*2+1)*16 + 8 + t];
    float m  = fmaxf(mA, mB);
    float eA = __expf(mA - m), eB = __expf(mB - m);
    float inv = 1.0f/(lA*eA + lB*eB);
    sA[t] = eA*inv; sB[t] = eB*inv;
  }
  __syncthreads();
  const float* cA = g_ctx2 + (size_t)(b*2)*NH*DINOD;
  const float* cB = g_ctx2 + (size_t)(b*2+1)*NH*DINOD;
  for(int i = t; i < NH*DINOD; i += 128){
    int h = i/DINOD;
    cs[i] = cA[i]*sA[h] + cB[i]*sB[h];
  }
  __syncthreads();
  int col = 4*t, h = col >> 6;               // 4 cols, all in head h
  const float* cp = cs + h*DINOD;
  float4 bvv = *(const float4*)(bv + col);
  unsigned long long acc01 = pk2(bvv.x, bvv.y), acc23 = pk2(bvv.z, bvv.w);
  #pragma unroll 4
  for(int c = 0; c < DINOD; c++){
    float4 w = *(const float4*)(Wv + (size_t)c*CLIPD + col);
    float cc = cp[c];
    unsigned long long ccp = pk2(cc, cc);
    fma2(acc01, pk2(w.x, w.y), ccp);
    fma2(acc23, pk2(w.z, w.w), ccp);
  }
  float2 P0 = upk2(acc01), P1 = upk2(acc23);
  float s = P0.x + P0.y + P1.x + P1.y;
  float q = P0.x*P0.x + P0.y*P0.y + P1.x*P1.x + P1.y*P1.y;
  #pragma unroll
  for(int o = 16; o; o >>= 1){
    s += __shfl_xor_sync(0xffffffffu, s, o);
    q += __shfl_xor_sync(0xffffffffu, q, o);
  }
  int wi = t>>5, lane = t&31;
  if(lane == 0){ red[0][wi] = s; red[1][wi] = q; }
  __syncthreads();
  float S  = red[0][0] + red[0][1] + red[0][2] + red[0][3];
  float Qq = red[1][0] + red[1][1] + red[1][2] + red[1][3];
  float mu = S*(1.0f/512.0f);
  float var = Qq*(1.0f/512.0f) - mu*mu;
  float rstd = rsqrtf(var + 1e-5f);
  float4 g4  = *(const float4*)(gamma + col);
  float4 be4 = *(const float4*)(beta + col);
  float4 o4;
  o4.x = (P0.x - mu)*rstd*g4.x + be4.x;
  o4.y = (P0.y - mu)*rstd*g4.y + be4.y;
  o4.z = (P1.x - mu)*rstd*g4.z + be4.z;
  o4.w = (P1.y - mu)*rstd*g4.w + be4.w;
  *(float4*)(out + (size_t)b*CLIPD + col) = o4;
}

extern "C" void kernel_launch(void* const* d_in, const int* in_sizes, int n_in,
                              void* d_out, int out_size) {
  const float* dino  = (const float*)d_in[0];
  const float* clip  = (const float*)d_in[1];
  const float* Wq    = (const float*)d_in[2];
  const float* bq    = (const float*)d_in[3];
  const float* Wk    = (const float*)d_in[4];
  // d_in[5] = bk: cancels in softmax
  const float* Wv    = (const float*)d_in[6];
  const float* bv    = (const float*)d_in[7];
  const float* temp  = (const float*)d_in[8];
  const float* gamma = (const float*)d_in[9];
  const float* beta  = (const float*)d_in[10];
  float* out = (float*)d_out;

  cudaFuncSetAttribute(k3_attn, cudaFuncAttributeMaxDynamicSharedMemorySize, SMEM3);

  k1_qproj<<<128, 128>>>(clip, Wq, bq);
  k2_qk<<<64, 384>>>(Wk, temp);
  k3_attn<<<256, 256, SMEM3>>>(dino);
  k4_out<<<128, 128>>>(Wv, bv, gamma, beta, out);
}